// round 9
// baseline (speedup 1.0000x reference)
#include <cuda_runtime.h>
#include <cstdint>

#define BATCH 16
#define CH    128
#define HGT   128
#define WID   128
#define NTHR  256

#define NSTAGE 24            // 3 kh * 8 ci-chunks (16 ci each)
#define A_F    3072          // floats of A per stage (fragment-packed)
#define B_CI_STRIDE 284      // floats per ci (2 rows of 136 + pad); 284 % 8 == 4 -> conflict-free LDS.128
#define B_ROW_OFF   136
#define SLOT_F (A_F + 16*B_CI_STRIDE)   // 7616 floats
#define SMEM_DYN (3*SLOT_F*4)           // 91392 B -> 2 CTAs/SM
#define EP_STRIDE 260                   // epilogue smem stride

__device__ float g_x [(size_t)BATCH*CH*HGT*WID];
__device__ float g_xr[(size_t)BATCH*CH*HGT*WID];
__device__ float g_t [(size_t)BATCH*CH*HGT*WID];
__device__ float g_wp[2*2*24*3072];   // [set][cohalf][stage][fragment-packed 3072]

// ---------- helpers ----------
__device__ __forceinline__ uint32_t smem_u32(const void* p){
    uint32_t a; asm("{ .reg .u64 t; cvta.to.shared.u64 t, %1; cvt.u32.u64 %0, t; }":"=r"(a):"l"(p));
    return a;
}
__device__ __forceinline__ float f2tf32(float f){
    uint32_t r; asm("cvt.rna.tf32.f32 %0, %1;":"=r"(r):"f"(f));
    return __uint_as_float(r);
}
__device__ __forceinline__ void cp16(uint32_t dst, const void* src, uint32_t ss){
    asm volatile("cp.async.cg.shared.global [%0], [%1], 16, %2;"
                 :: "r"(dst), "l"(src), "r"(ss) : "memory");
}
#define CP_COMMIT() asm volatile("cp.async.commit_group;":::"memory")
template<int N> __device__ __forceinline__ void cp_wait(){
    asm volatile("cp.async.wait_group %0;"::"n"(N):"memory");
}
__device__ __forceinline__ void mma8(float* d, const float4& a, uint32_t b0, uint32_t b1){
    asm volatile("mma.sync.aligned.m16n8k8.row.col.f32.tf32.tf32.f32 "
        "{%0,%1,%2,%3}, {%4,%5,%6,%7}, {%8,%9}, {%0,%1,%2,%3};"
        : "+f"(d[0]), "+f"(d[1]), "+f"(d[2]), "+f"(d[3])
        : "r"(__float_as_uint(a.x)), "r"(__float_as_uint(a.y)),
          "r"(__float_as_uint(a.z)), "r"(__float_as_uint(a.w)),
          "r"(b0), "r"(b1));
}

// ---------- weight pack: per-lane MMA fragment layout (unchanged mapping) ----------
__global__ void pack_w(const float* __restrict__ w1, const float* __restrict__ w2,
                       float* __restrict__ dst){
    int idx = blockIdx.x*blockDim.x + threadIdx.x;
    if (idx >= 2*147456) return;
    int r = idx;
    int set = r / 147456; r %= 147456;
    int ch  = r / 73728;  r %= 73728;
    int s   = r / 3072;   r %= 3072;
    int kw  = r / 1024;   r %= 1024;
    int k8  = r / 512;    r %= 512;
    int m16 = r / 128;    r %= 128;
    int lane= r >> 2;
    int j   = r & 3;
    int g = lane>>2, t = lane&3;
    int co   = ch*64 + m16*16 + g + ((j&1)<<3);
    int kcol = t + ((j>>1)<<2);
    int kh = s>>3, chunk = s&7;
    int ci = chunk*16 + k8*8 + kcol;
    const float* w = set ? w2 : w1;
    dst[idx] = f2tf32(w[(size_t)co*(CH*9) + ci*9 + kh*3 + kw]);
}

// ---------- round pre-pass ----------
__global__ void round_x(const float4* __restrict__ in, float4* __restrict__ out, int n4){
    for (int i = blockIdx.x*blockDim.x + threadIdx.x; i < n4; i += gridDim.x*blockDim.x){
        float4 v = in[i];
        v.x = f2tf32(v.x); v.y = f2tf32(v.y); v.z = f2tf32(v.z); v.w = f2tf32(v.w);
        out[i] = v;
    }
}

// ---------- conv kernel ----------
// MODE 0: out = rna(relu(conv+b))
// MODE 1: v = xadd + (conv+b)/3 ; out = v ; out2 = rna(v)
// MODE 2: out = relu(xadd + (conv+b)/3)
template<int MODE>
__global__ void __launch_bounds__(NTHR, 2)
conv_mma(const float* __restrict__ in, const float* __restrict__ wp,
         const float* __restrict__ bias, const float* __restrict__ xadd,
         float* __restrict__ out, float* __restrict__ out2)
{
    extern __shared__ __align__(1024) float sm[];
    const int tid = threadIdx.x, lane = tid&31, wid = tid>>5;
    const int g = lane>>2, t = lane&3;
    const int wm = wid&1, wn = wid>>1;        // wm: m-half of 64co ; wn: 0..3
    const int brow = wn>>1, nb = (wn&1)*64;   // input-row sel + px window base
    const int h0 = blockIdx.x*2, b = blockIdx.y, ch = blockIdx.z;
    const float* in_b = in + (size_t)b*CH*HGT*WID;
    const float* wpc  = wp + (size_t)ch*73728;

    float d[2][8][4];
#pragma unroll
    for (int mt=0;mt<2;mt++)
#pragma unroll
        for (int nt=0;nt<8;nt++)
#pragma unroll
            for (int c=0;c<4;c++) d[mt][nt][c] = 0.f;

    auto issue_stage = [&](int s, int slot){
        float* sl = sm + slot*SLOT_F;
        uint32_t base = smem_u32(sl);
        // A: fragment-packed, contiguous copy (12288 B = 768 cp16)
        const float4* asrc = (const float4*)(wpc + (size_t)s*A_F);
#pragma unroll
        for (int i=0;i<3;i++){
            int u = tid + i*256;
            cp16(base + u*16, asrc + u, 16);
        }
        // B: 16 ci x 2 rows x 128 floats = 1024 cp16 (4 per thread)
        const int kh = s>>3, chunk = s&7;
#pragma unroll
        for (int i=0;i<4;i++){
            int v = tid + i*256;
            int ci = v>>6, rem = v&63, row = rem>>5, cw = rem&31;
            int r = h0 + kh - 1 + row;
            uint32_t ss = ((unsigned)r < HGT) ? 16u : 0u;
            int rc = ((unsigned)r < HGT) ? r : 0;
            const float* src = in_b + ((size_t)(chunk*16+ci)*HGT + rc)*WID + cw*4;
            cp16(base + A_F*4 + ci*(B_CI_STRIDE*4) + row*544 + 16 + cw*16, src, ss);
        }
        // halo edge floats (w=-1 at idx 3, w=128 at idx 132): always zero
        if (tid < 64){
            int ci = tid>>2, rem = tid&3, row = rem>>1;
            sl[A_F + ci*B_CI_STRIDE + row*B_ROW_OFF + ((rem&1)?132:3)] = 0.f;
        }
    };

    issue_stage(0, 0); CP_COMMIT();
    issue_stage(1, 1); CP_COMMIT();

    int slot = 0;
    for (int s=0; s<NSTAGE; s++){
        if (s < NSTAGE-2) cp_wait<1>(); else cp_wait<0>();
        __syncthreads();

        const float* A  = sm + slot*SLOT_F;
        const float* Bb = A + A_F;
#pragma unroll
        for (int k8=0; k8<2; k8++){
            // load 13-float windows for the two k-rows of this k8 slice
            const float* pr0 = Bb + (k8*8 + t)*B_CI_STRIDE + brow*B_ROW_OFF + nb + 8*g;
            const float* pr1 = pr0 + 4*B_CI_STRIDE;
            float r0f[13], r1f[13];
            *(float4*)&r0f[0] = *(const float4*)&pr0[0];
            *(float4*)&r0f[4] = *(const float4*)&pr0[4];
            *(float4*)&r0f[8] = *(const float4*)&pr0[8];
            r0f[12] = pr0[12];
            *(float4*)&r1f[0] = *(const float4*)&pr1[0];
            *(float4*)&r1f[4] = *(const float4*)&pr1[4];
            *(float4*)&r1f[8] = *(const float4*)&pr1[8];
            r1f[12] = pr1[12];
#pragma unroll
            for (int kw=0; kw<3; kw++){
                float4 av[2];
#pragma unroll
                for (int mt=0; mt<2; mt++)
                    av[mt] = *(const float4*)(A + ((kw*2+k8)*4 + wm*2+mt)*128 + lane*4);
#pragma unroll
                for (int nt=0; nt<8; nt++){
                    uint32_t b0 = __float_as_uint(r0f[3+nt+kw]);
                    uint32_t b1 = __float_as_uint(r1f[3+nt+kw]);
                    mma8(d[0][nt], av[0], b0, b1);
                    mma8(d[1][nt], av[1], b0, b1);
                }
            }
        }

        if (s < NSTAGE-2){
            int nslot = slot+2; if (nslot >= 3) nslot -= 3;
            issue_stage(s+2, nslot);
            CP_COMMIT();
        }
        slot = (slot+1 == 3) ? 0 : slot+1;
    }

    // ---- epilogue: accums -> smem [64co][256px] -> coalesced gmem ----
    __syncthreads();
    float* eb = sm;
#pragma unroll
    for (int mt=0; mt<2; mt++){
        const int r0 = wm*32 + mt*16 + g;
        const float bv0 = bias[ch*64 + r0];
        const float bv1 = bias[ch*64 + r0 + 8];
        const int a0 = r0*EP_STRIDE + brow*128 + nb + 16*t;
#pragma unroll
        for (int nt=0; nt<8; nt++){
            eb[a0 + nt]               = d[mt][nt][0] + bv0;   // col 2t   -> px nb+16t+nt
            eb[a0 + 8 + nt]           = d[mt][nt][1] + bv0;   // col 2t+1 -> px nb+16t+8+nt
            eb[a0 + 8*EP_STRIDE + nt]     = d[mt][nt][2] + bv1;
            eb[a0 + 8*EP_STRIDE + 8 + nt] = d[mt][nt][3] + bv1;
        }
    }
    __syncthreads();

    const float inv3 = 1.0f/3.0f;
    for (int it = tid; it < 64*64; it += NTHR){
        int co = it>>6, p4 = it&63;
        float4 v = *(const float4*)&eb[co*EP_STRIDE + p4*4];
        int hh = h0 + (p4>>5), w = (p4&31)*4;
        size_t gi = (((size_t)b*CH + ch*64 + co)*HGT + hh)*WID + w;
        if (MODE == 0){
            v.x = f2tf32(fmaxf(v.x,0.f)); v.y = f2tf32(fmaxf(v.y,0.f));
            v.z = f2tf32(fmaxf(v.z,0.f)); v.w = f2tf32(fmaxf(v.w,0.f));
            *(float4*)&out[gi] = v;
        } else {
            float4 xv = *(const float4*)&xadd[gi];
            v.x = xv.x + inv3*v.x; v.y = xv.y + inv3*v.y;
            v.z = xv.z + inv3*v.z; v.w = xv.w + inv3*v.w;
            if (MODE == 2){
                v.x = fmaxf(v.x,0.f); v.y = fmaxf(v.y,0.f);
                v.z = fmaxf(v.z,0.f); v.w = fmaxf(v.w,0.f);
            }
            *(float4*)&out[gi] = v;
            if (MODE == 1){
                float4 rv;
                rv.x = f2tf32(v.x); rv.y = f2tf32(v.y);
                rv.z = f2tf32(v.z); rv.w = f2tf32(v.w);
                *(float4*)&out2[gi] = rv;
            }
        }
    }
}

// ---------- launch ----------
extern "C" void kernel_launch(void* const* d_in, const int* in_sizes, int n_in,
                              void* d_out, int out_size)
{
    const float* x  = (const float*)d_in[0];
    const float* w1 = (const float*)d_in[1];
    const float* b1 = (const float*)d_in[2];
    const float* w2 = (const float*)d_in[3];
    const float* b2 = (const float*)d_in[4];
    float* out = (float*)d_out;

    float *gx, *gxr, *gt, *gwp;
    cudaGetSymbolAddress((void**)&gx,  g_x);
    cudaGetSymbolAddress((void**)&gxr, g_xr);
    cudaGetSymbolAddress((void**)&gt,  g_t);
    cudaGetSymbolAddress((void**)&gwp, g_wp);

    cudaFuncSetAttribute(conv_mma<0>, cudaFuncAttributeMaxDynamicSharedMemorySize, SMEM_DYN);
    cudaFuncSetAttribute(conv_mma<1>, cudaFuncAttributeMaxDynamicSharedMemorySize, SMEM_DYN);
    cudaFuncSetAttribute(conv_mma<2>, cudaFuncAttributeMaxDynamicSharedMemorySize, SMEM_DYN);

    pack_w<<<(2*147456 + 255)/256, 256>>>(w1, w2, gwp);
    round_x<<<4096, 256>>>((const float4*)x, (float4*)gxr, (int)((size_t)BATCH*CH*HGT*WID/4));

    const float* wp1 = gwp;
    const float* wp2 = gwp + 147456;
    dim3 grid(HGT/2, BATCH, 2);

    conv_mma<0><<<grid, NTHR, SMEM_DYN>>>(gxr, wp1, b1, nullptr, gt,  nullptr);
    conv_mma<1><<<grid, NTHR, SMEM_DYN>>>(gt,  wp2, b2, x,       gx,  gxr);
    conv_mma<0><<<grid, NTHR, SMEM_DYN>>>(gxr, wp1, b1, nullptr, gt,  nullptr);
    conv_mma<1><<<grid, NTHR, SMEM_DYN>>>(gt,  wp2, b2, gx,      gx,  gxr);
    conv_mma<0><<<grid, NTHR, SMEM_DYN>>>(gxr, wp1, b1, nullptr, gt,  nullptr);
    conv_mma<2><<<grid, NTHR, SMEM_DYN>>>(gt,  wp2, b2, gx,      out, nullptr);
}

// round 10
// speedup vs baseline: 1.0360x; 1.0360x over previous
#include <cuda_runtime.h>
#include <cstdint>

#define BATCH 16
#define CH    128
#define HGT   128
#define WID   128
#define NTHR  256

#define NSTAGE 24            // 3 kh * 8 ci-chunks (16 ci each)
#define A_F    3072          // floats of A per stage (fragment-packed)
#define B_CI_STRIDE 288      // floats per ci (2 rows of 136, padded; mult of 32 -> block aligned)
#define SLOT_F (A_F + 16*B_CI_STRIDE)   // 7680 floats = 30720 B
#define SMEM_DYN (3*SLOT_F*4)           // 92160 B -> 2 CTAs/SM
#define EP_STRIDE 260                   // epilogue smem stride

__device__ float g_x [(size_t)BATCH*CH*HGT*WID];
__device__ float g_xr[(size_t)BATCH*CH*HGT*WID];
__device__ float g_t [(size_t)BATCH*CH*HGT*WID];
__device__ float g_wp[2*2*24*3072];   // [set][cohalf][stage][fragment-packed 3072]

// ---------- helpers ----------
__device__ __forceinline__ uint32_t smem_u32(const void* p){
    uint32_t a; asm("{ .reg .u64 t; cvta.to.shared.u64 t, %1; cvt.u32.u64 %0, t; }":"=r"(a):"l"(p));
    return a;
}
__device__ __forceinline__ float f2tf32(float f){
    uint32_t r; asm("cvt.rna.tf32.f32 %0, %1;":"=r"(r):"f"(f));
    return __uint_as_float(r);
}
__device__ __forceinline__ void cp16(uint32_t dst, const void* src, uint32_t ss){
    asm volatile("cp.async.cg.shared.global [%0], [%1], 16, %2;"
                 :: "r"(dst), "l"(src), "r"(ss) : "memory");
}
#define CP_COMMIT() asm volatile("cp.async.commit_group;":::"memory")
template<int N> __device__ __forceinline__ void cp_wait(){
    asm volatile("cp.async.wait_group %0;"::"n"(N):"memory");
}
__device__ __forceinline__ void mma8(float* d, const float4& a, uint32_t b0, uint32_t b1){
    asm volatile("mma.sync.aligned.m16n8k8.row.col.f32.tf32.tf32.f32 "
        "{%0,%1,%2,%3}, {%4,%5,%6,%7}, {%8,%9}, {%0,%1,%2,%3};"
        : "+f"(d[0]), "+f"(d[1]), "+f"(d[2]), "+f"(d[3])
        : "r"(__float_as_uint(a.x)), "r"(__float_as_uint(a.y)),
          "r"(__float_as_uint(a.z)), "r"(__float_as_uint(a.w)),
          "r"(b0), "r"(b1));
}
// XOR group swizzle: f(u) in {0,1,4,5} ; phys word for logical word L, channel key u=ci&3
__device__ __forceinline__ int bswz(int L, int u){
    int f = (u&1) | ((u&2)<<1);
    return (L & ~31) | ((((L>>2)&7) ^ f)<<2) | (L&3);
}

// ---------- weight pack: per-lane MMA fragment layout ----------
__global__ void pack_w(const float* __restrict__ w1, const float* __restrict__ w2,
                       float* __restrict__ dst){
    int idx = blockIdx.x*blockDim.x + threadIdx.x;
    if (idx >= 2*147456) return;
    int r = idx;
    int set = r / 147456; r %= 147456;
    int ch  = r / 73728;  r %= 73728;
    int s   = r / 3072;   r %= 3072;
    int kw  = r / 1024;   r %= 1024;
    int k8  = r / 512;    r %= 512;
    int m16 = r / 128;    r %= 128;
    int lane= r >> 2;
    int j   = r & 3;
    int g = lane>>2, t = lane&3;
    int co   = ch*64 + m16*16 + g + ((j&1)<<3);
    int kcol = t + ((j>>1)<<2);
    int kh = s>>3, chunk = s&7;
    int ci = chunk*16 + k8*8 + kcol;
    const float* w = set ? w2 : w1;
    dst[idx] = f2tf32(w[(size_t)co*(CH*9) + ci*9 + kh*3 + kw]);
}

// ---------- round pre-pass ----------
__global__ void round_x(const float4* __restrict__ in, float4* __restrict__ out, int n4){
    for (int i = blockIdx.x*blockDim.x + threadIdx.x; i < n4; i += gridDim.x*blockDim.x){
        float4 v = in[i];
        v.x = f2tf32(v.x); v.y = f2tf32(v.y); v.z = f2tf32(v.z); v.w = f2tf32(v.w);
        out[i] = v;
    }
}

// ---------- conv kernel ----------
// MODE 0: out = rna(relu(conv+b))
// MODE 1: v = xadd + (conv+b)/3 ; out = v ; out2 = rna(v)
// MODE 2: out = relu(xadd + (conv+b)/3)
template<int MODE>
__global__ void __launch_bounds__(NTHR, 2)
conv_mma(const float* __restrict__ in, const float* __restrict__ wp,
         const float* __restrict__ bias, const float* __restrict__ xadd,
         float* __restrict__ out, float* __restrict__ out2)
{
    extern __shared__ __align__(1024) float sm[];
    const int tid = threadIdx.x, lane = tid&31, wid = tid>>5;
    const int g = lane>>2, t = lane&3;
    const int wm = wid&1, wn = wid>>1;        // wm: m-half of 64co ; wn: 0..3
    const int brow = wn>>1, nb = (wn&1)*64;   // input-row sel + px window base
    const int h0 = blockIdx.x*2, b = blockIdx.y, ch = blockIdx.z;
    const float* in_b = in + (size_t)b*CH*HGT*WID;
    const float* wpc  = wp + (size_t)ch*73728;

    float d[2][8][4];
#pragma unroll
    for (int mt=0;mt<2;mt++)
#pragma unroll
        for (int nt=0;nt<8;nt++)
#pragma unroll
            for (int c=0;c<4;c++) d[mt][nt][c] = 0.f;

    auto issue_stage = [&](int s, int slot){
        float* sl = sm + slot*SLOT_F;
        uint32_t base = smem_u32(sl);
        // A: fragment-packed, contiguous copy (12288 B = 768 cp16)
        const float4* asrc = (const float4*)(wpc + (size_t)s*A_F);
#pragma unroll
        for (int i=0;i<3;i++){
            int u = tid + i*256;
            cp16(base + u*16, asrc + u, 16);
        }
        // B: 16 ci x 2 rows x 128 px, swizzled 16B chunks. px p <-> word p+4 per row.
        const int kh = s>>3, chunk = s&7;
#pragma unroll
        for (int i=0;i<4;i++){
            int v = tid + i*256;
            int ci = v>>6, rem = v&63, row = rem>>5, cw = rem&31;
            int L = row*136 + 4 + cw*4;
            int phys = bswz(L, ci&3);
            int r = h0 + kh - 1 + row;
            uint32_t ss = ((unsigned)r < HGT) ? 16u : 0u;
            int rc = ((unsigned)r < HGT) ? r : 0;
            const float* src = in_b + ((size_t)(chunk*16+ci)*HGT + rc)*WID + cw*4;
            cp16(base + (A_F + ci*B_CI_STRIDE + phys)*4, src, ss);
        }
        // halo zeros: words 3 (px -1) and 132 (px 128) in each row
        if (tid < 64){
            int ci = tid>>2, rem = tid&3, row = rem>>1;
            int L = row*136 + ((rem&1) ? 132 : 3);
            sl[A_F + ci*B_CI_STRIDE + bswz(L, ci&3)] = 0.f;
        }
    };

    issue_stage(0, 0); CP_COMMIT();
    issue_stage(1, 1); CP_COMMIT();

    const int ft = (t&1) | ((t&2)<<1);
    const int Lbase = brow*136 + nb + 8*g;

    int slot = 0;
    for (int s=0; s<NSTAGE; s++){
        if (s < NSTAGE-2) cp_wait<1>(); else cp_wait<0>();
        __syncthreads();

        const float* A  = sm + slot*SLOT_F;
        const float* Bb = A + A_F;
#pragma unroll
        for (int k8=0; k8<2; k8++){
            const float* B0 = Bb + (k8*8 + t)*B_CI_STRIDE;
            const float* B1 = B0 + 4*B_CI_STRIDE;
            float w0[16], w1[16];
#pragma unroll
            for (int c=0; c<4; c++){
                int L = Lbase + 4*c;
                int phys = (L & ~31) | ((((L>>2)&7) ^ ft)<<2);
                *(float4*)&w0[c*4] = *(const float4*)(B0 + phys);
                *(float4*)&w1[c*4] = *(const float4*)(B1 + phys);
            }
#pragma unroll
            for (int kw=0; kw<3; kw++){
                float4 av[2];
#pragma unroll
                for (int mt=0; mt<2; mt++)
                    av[mt] = *(const float4*)(A + ((kw*2+k8)*4 + wm*2+mt)*128 + lane*4);
#pragma unroll
                for (int nt=0; nt<8; nt++){
                    uint32_t b0 = __float_as_uint(w0[3+nt+kw]);
                    uint32_t b1 = __float_as_uint(w1[3+nt+kw]);
                    mma8(d[0][nt], av[0], b0, b1);
                    mma8(d[1][nt], av[1], b0, b1);
                }
            }
        }

        if (s < NSTAGE-2){
            int nslot = slot+2; if (nslot >= 3) nslot -= 3;
            issue_stage(s+2, nslot);
            CP_COMMIT();
        }
        slot = (slot+1 == 3) ? 0 : slot+1;
    }

    // ---- epilogue: accums -> smem [64co][256px] -> coalesced gmem ----
    __syncthreads();
    float* eb = sm;
#pragma unroll
    for (int mt=0; mt<2; mt++){
        const int r0 = wm*32 + mt*16 + g;
        const float bv0 = bias[ch*64 + r0];
        const float bv1 = bias[ch*64 + r0 + 8];
        const int a0 = r0*EP_STRIDE + brow*128 + nb + 16*t;
#pragma unroll
        for (int nt=0; nt<8; nt++){
            eb[a0 + nt]                   = d[mt][nt][0] + bv0;   // col 2t   -> px nb+16t+nt
            eb[a0 + 8 + nt]               = d[mt][nt][1] + bv0;   // col 2t+1 -> px nb+16t+8+nt
            eb[a0 + 8*EP_STRIDE + nt]     = d[mt][nt][2] + bv1;
            eb[a0 + 8*EP_STRIDE + 8 + nt] = d[mt][nt][3] + bv1;
        }
    }
    __syncthreads();

    const float inv3 = 1.0f/3.0f;
    for (int it = tid; it < 64*64; it += NTHR){
        int co = it>>6, p4 = it&63;
        float4 v = *(const float4*)&eb[co*EP_STRIDE + p4*4];
        int hh = h0 + (p4>>5), w = (p4&31)*4;
        size_t gi = (((size_t)b*CH + ch*64 + co)*HGT + hh)*WID + w;
        if (MODE == 0){
            v.x = f2tf32(fmaxf(v.x,0.f)); v.y = f2tf32(fmaxf(v.y,0.f));
            v.z = f2tf32(fmaxf(v.z,0.f)); v.w = f2tf32(fmaxf(v.w,0.f));
            *(float4*)&out[gi] = v;
        } else {
            float4 xv = *(const float4*)&xadd[gi];
            v.x = xv.x + inv3*v.x; v.y = xv.y + inv3*v.y;
            v.z = xv.z + inv3*v.z; v.w = xv.w + inv3*v.w;
            if (MODE == 2){
                v.x = fmaxf(v.x,0.f); v.y = fmaxf(v.y,0.f);
                v.z = fmaxf(v.z,0.f); v.w = fmaxf(v.w,0.f);
            }
            *(float4*)&out[gi] = v;
            if (MODE == 1){
                float4 rv;
                rv.x = f2tf32(v.x); rv.y = f2tf32(v.y);
                rv.z = f2tf32(v.z); rv.w = f2tf32(v.w);
                *(float4*)&out2[gi] = rv;
            }
        }
    }
}

// ---------- launch ----------
extern "C" void kernel_launch(void* const* d_in, const int* in_sizes, int n_in,
                              void* d_out, int out_size)
{
    const float* x  = (const float*)d_in[0];
    const float* w1 = (const float*)d_in[1];
    const float* b1 = (const float*)d_in[2];
    const float* w2 = (const float*)d_in[3];
    const float* b2 = (const float*)d_in[4];
    float* out = (float*)d_out;

    float *gx, *gxr, *gt, *gwp;
    cudaGetSymbolAddress((void**)&gx,  g_x);
    cudaGetSymbolAddress((void**)&gxr, g_xr);
    cudaGetSymbolAddress((void**)&gt,  g_t);
    cudaGetSymbolAddress((void**)&gwp, g_wp);

    cudaFuncSetAttribute(conv_mma<0>, cudaFuncAttributeMaxDynamicSharedMemorySize, SMEM_DYN);
    cudaFuncSetAttribute(conv_mma<1>, cudaFuncAttributeMaxDynamicSharedMemorySize, SMEM_DYN);
    cudaFuncSetAttribute(conv_mma<2>, cudaFuncAttributeMaxDynamicSharedMemorySize, SMEM_DYN);

    pack_w<<<(2*147456 + 255)/256, 256>>>(w1, w2, gwp);
    round_x<<<4096, 256>>>((const float4*)x, (float4*)gxr, (int)((size_t)BATCH*CH*HGT*WID/4));

    const float* wp1 = gwp;
    const float* wp2 = gwp + 147456;
    dim3 grid(HGT/2, BATCH, 2);

    conv_mma<0><<<grid, NTHR, SMEM_DYN>>>(gxr, wp1, b1, nullptr, gt,  nullptr);
    conv_mma<1><<<grid, NTHR, SMEM_DYN>>>(gt,  wp2, b2, x,       gx,  gxr);
    conv_mma<0><<<grid, NTHR, SMEM_DYN>>>(gxr, wp1, b1, nullptr, gt,  nullptr);
    conv_mma<1><<<grid, NTHR, SMEM_DYN>>>(gt,  wp2, b2, gx,      gx,  gxr);
    conv_mma<0><<<grid, NTHR, SMEM_DYN>>>(gxr, wp1, b1, nullptr, gt,  nullptr);
    conv_mma<2><<<grid, NTHR, SMEM_DYN>>>(gt,  wp2, b2, gx,      out, nullptr);
}

// round 13
// speedup vs baseline: 2.0855x; 2.0132x over previous
#include <cuda_runtime.h>
#include <cuda_fp16.h>
#include <cstdint>

#define BATCH 16
#define CH    128
#define HGT   128
#define WID   128
#define NTHR  256

#define NSTAGE 12              // 3 kh * 4 ci-chunks (32 ci each)
#define A_W    3072            // 32-bit words of A per stage (fragment-packed half2)
#define B_CI2_STRIDE 280       // words per ci2 (2 rows of 136 + pad); conflict-free
#define SLOT_W (A_W + 16*B_CI2_STRIDE)   // 7552 words = 30.2KB
#define SMEM_DYN (3*SLOT_W*4)            // 90624 B -> 2 CTAs/SM
#define EP_STRIDE 260

__device__ float    g_x  [(size_t)BATCH*CH*HGT*WID];     // fp32 state
__device__ uint32_t g_xh [(size_t)BATCH*64*HGT*WID];     // half2 channel-pair x
__device__ uint32_t g_th [(size_t)BATCH*64*HGT*WID];     // half2 channel-pair t
__device__ uint32_t g_wph[2*2*12*3072];                  // packed fp16 weights

// ---------- helpers ----------
__device__ __forceinline__ uint32_t smem_u32(const void* p){
    uint32_t a; asm("{ .reg .u64 t; cvta.to.shared.u64 t, %1; cvt.u32.u64 %0, t; }":"=r"(a):"l"(p));
    return a;
}
__device__ __forceinline__ void cp16(uint32_t dst, const void* src, uint32_t ss){
    asm volatile("cp.async.cg.shared.global [%0], [%1], 16, %2;"
                 :: "r"(dst), "l"(src), "r"(ss) : "memory");
}
#define CP_COMMIT() asm volatile("cp.async.commit_group;":::"memory")
template<int N> __device__ __forceinline__ void cp_wait(){
    asm volatile("cp.async.wait_group %0;"::"n"(N):"memory");
}
__device__ __forceinline__ void mma16(float* d, const uint4& a, uint32_t b0, uint32_t b1){
    asm volatile("mma.sync.aligned.m16n8k16.row.col.f32.f16.f16.f32 "
        "{%0,%1,%2,%3}, {%4,%5,%6,%7}, {%8,%9}, {%0,%1,%2,%3};"
        : "+f"(d[0]), "+f"(d[1]), "+f"(d[2]), "+f"(d[3])
        : "r"(a.x), "r"(a.y), "r"(a.z), "r"(a.w), "r"(b0), "r"(b1));
}
// pack two fp32 -> half2 word, low half = lo  (cvt.rn.f16x2.f32 d,a,b : d.lo=cvt(b), d.hi=cvt(a))
__device__ __forceinline__ uint32_t pk2(float lo, float hi){
    uint32_t r;
    asm("cvt.rn.f16x2.f32 %0, %1, %2;" : "=r"(r) : "f"(hi), "f"(lo));
    return r;
}

// ---------- weight pack: fp16 fragment layout ----------
// word idx: [set][ch][s(12)][kw(3)][j(2)][m16(4)][lane(32)][r(4)]
__global__ void pack_wh(const float* __restrict__ w1, const float* __restrict__ w2,
                        uint32_t* __restrict__ dst){
    int idx = blockIdx.x*blockDim.x + threadIdx.x;
    if (idx >= 2*73728) return;
    int r = idx;
    int set = r / 73728; r %= 73728;
    int ch  = r / 36864; r %= 36864;
    int s   = r / 3072;  r %= 3072;
    int kw  = r / 1024;  r %= 1024;
    int j   = r / 512;   r %= 512;
    int m16 = r / 128;   r %= 128;
    int lane = r >> 2;
    int rr   = r & 3;
    int g = lane>>2, t = lane&3;
    int co = ch*64 + m16*16 + g + ((rr&1)<<3);
    int kh = s>>2, chunk = s&3;
    int ci = chunk*32 + j*16 + 2*t + ((rr>>1)<<3);
    const float* w = set ? w2 : w1;
    float lo = w[((size_t)co*CH + ci  )*9 + kh*3 + kw];
    float hi = w[((size_t)co*CH + ci+1)*9 + kh*3 + kw];
    dst[idx] = pk2(lo, hi);
}

// ---------- convert x -> channel-pair half2 ----------
__global__ void convert_x(const float* __restrict__ in, uint32_t* __restrict__ out){
    const int total = BATCH*64*HGT*(WID/4);
    for (int i = blockIdx.x*blockDim.x + threadIdx.x; i < total; i += gridDim.x*blockDim.x){
        int w4 = i & 31, r = i >> 5;
        int h  = r & 127; r >>= 7;
        int c2 = r & 63;  int b = r >> 6;
        const float* p0 = in + (((size_t)b*CH + 2*c2  )*HGT + h)*WID + w4*4;
        const float* p1 = p0 + (size_t)HGT*WID;
        float4 lo = *(const float4*)p0;
        float4 hi = *(const float4*)p1;
        uint4 o;
        o.x = pk2(lo.x, hi.x); o.y = pk2(lo.y, hi.y);
        o.z = pk2(lo.z, hi.z); o.w = pk2(lo.w, hi.w);
        *(uint4*)(out + (((size_t)b*64 + c2)*HGT + h)*WID + w4*4) = o;
    }
}

// ---------- conv kernel ----------
// MODE 0: t = relu(conv+b)            -> outh only
// MODE 1: v = xadd + (conv+b)/3       -> outf (fp32) + outh (half2)
// MODE 2: v = relu(xadd + (conv+b)/3) -> outf only
template<int MODE>
__global__ void __launch_bounds__(NTHR, 2)
conv_mma(const uint32_t* __restrict__ inh, const uint32_t* __restrict__ wph,
         const float* __restrict__ bias, const float* __restrict__ xadd,
         float* __restrict__ outf, uint32_t* __restrict__ outh)
{
    extern __shared__ __align__(1024) float sm[];
    uint32_t* smw = (uint32_t*)sm;
    const int tid = threadIdx.x, lane = tid&31, wid = tid>>5;
    const int g = lane>>2, t = lane&3;
    const int wm = wid&1, wn = wid>>1;
    const int brow = wn>>1, nb = (wn&1)*64;
    const int h0 = blockIdx.x*2, b = blockIdx.y, ch = blockIdx.z;
    const uint32_t* in_b = inh + (size_t)b*64*HGT*WID;
    const uint32_t* wpc  = wph + (size_t)ch*36864;

    float d[2][8][4];
#pragma unroll
    for (int mt=0;mt<2;mt++)
#pragma unroll
        for (int nt=0;nt<8;nt++)
#pragma unroll
            for (int c=0;c<4;c++) d[mt][nt][c] = 0.f;

    auto issue_stage = [&](int s, int slot){
        uint32_t* sl = smw + slot*SLOT_W;
        uint32_t base = smem_u32(sl);
        // A: 3072 words = 768 cp16
        const uint32_t* asrc = wpc + (size_t)s*3072;
#pragma unroll
        for (int i=0;i<3;i++){
            int u = tid + i*256;
            cp16(base + u*16, asrc + u*4, 16);
        }
        // B: 16 ci2 x 2 rows x 128 half2 = 1024 cp16
        const int kh = s>>2, chunk = s&3;
#pragma unroll
        for (int i=0;i<4;i++){
            int v = tid + i*256;
            int ci2 = v>>6, rem = v&63, row = rem>>5, cw = rem&31;
            int r = h0 + kh - 1 + row;
            uint32_t ss = ((unsigned)r < HGT) ? 16u : 0u;
            int rc = ((unsigned)r < HGT) ? r : 0;
            const uint32_t* src = in_b + ((size_t)(chunk*16+ci2)*HGT + rc)*WID + cw*4;
            cp16(base + (A_W + ci2*B_CI2_STRIDE + row*136 + 4 + cw*4)*4, src, ss);
        }
        // halo zeros: words 3 (px=-1) and 132 (px=128) per row
        if (tid < 64){
            int ci2 = tid>>2, rem = tid&3, row = rem>>1;
            sl[A_W + ci2*B_CI2_STRIDE + row*136 + ((rem&1)?132:3)] = 0;
        }
    };

    issue_stage(0, 0); CP_COMMIT();
    issue_stage(1, 1); CP_COMMIT();

    int slot = 0;
    for (int s=0; s<NSTAGE; s++){
        if (s < NSTAGE-2) cp_wait<1>(); else cp_wait<0>();
        __syncthreads();

        const uint32_t* A  = smw + slot*SLOT_W;
        const uint32_t* Bb = A + A_W;
#pragma unroll
        for (int j=0; j<2; j++){
            const uint32_t* bt = Bb + (j*8+t)*B_CI2_STRIDE + brow*136 + 3 + nb + g;
#pragma unroll
            for (int kw=0; kw<3; kw++){
                uint4 av[2];
#pragma unroll
                for (int mt=0; mt<2; mt++)
                    av[mt] = *(const uint4*)(A + ((kw*2+j)*4 + wm*2+mt)*128 + lane*4);
                const uint32_t* bp = bt + kw;
#pragma unroll
                for (int nt=0; nt<8; nt++){
                    uint32_t b0 = bp[nt*8];
                    uint32_t b1 = bp[nt*8 + 4*B_CI2_STRIDE];
                    mma16(d[0][nt], av[0], b0, b1);
                    mma16(d[1][nt], av[1], b0, b1);
                }
            }
        }

        if (s < NSTAGE-2){
            int nslot = slot+2; if (nslot >= 3) nslot -= 3;
            issue_stage(s+2, nslot);
            CP_COMMIT();
        }
        slot = (slot+1 == 3) ? 0 : slot+1;
    }

    // ---- epilogue ----
    __syncthreads();
    float* eb = sm;   // 64co x 256px, stride EP_STRIDE
#pragma unroll
    for (int mt=0; mt<2; mt++){
        const int r0 = wm*32 + mt*16 + g;
        const float bv0 = bias[ch*64 + r0];
        const float bv1 = bias[ch*64 + r0 + 8];
        const int a0 = r0*EP_STRIDE + brow*128 + nb + 2*t;
#pragma unroll
        for (int nt=0; nt<8; nt++){
            float v0 = d[mt][nt][0] + bv0, v1 = d[mt][nt][1] + bv0;
            float v2 = d[mt][nt][2] + bv1, v3 = d[mt][nt][3] + bv1;
            if (MODE == 0){
                v0 = fmaxf(v0,0.f); v1 = fmaxf(v1,0.f);
                v2 = fmaxf(v2,0.f); v3 = fmaxf(v3,0.f);
            }
            eb[a0 + nt*8]                  = v0;
            eb[a0 + nt*8 + 1]              = v1;
            eb[a0 + 8*EP_STRIDE + nt*8]    = v2;
            eb[a0 + 8*EP_STRIDE + nt*8 +1] = v3;
        }
    }
    __syncthreads();

    const float inv3 = 1.0f/3.0f;
    if (MODE != 0){
        for (int it = tid; it < 64*64; it += NTHR){
            int co = it>>6, p4 = it&63;
            float4 v = *(const float4*)&eb[co*EP_STRIDE + p4*4];
            int hh = h0 + (p4>>5), w = (p4&31)*4;
            size_t gi = (((size_t)b*CH + ch*64 + co)*HGT + hh)*WID + w;
            float4 xv = *(const float4*)&xadd[gi];
            v.x = xv.x + inv3*v.x; v.y = xv.y + inv3*v.y;
            v.z = xv.z + inv3*v.z; v.w = xv.w + inv3*v.w;
            if (MODE == 2){
                v.x = fmaxf(v.x,0.f); v.y = fmaxf(v.y,0.f);
                v.z = fmaxf(v.z,0.f); v.w = fmaxf(v.w,0.f);
            }
            *(float4*)&outf[gi] = v;
            if (MODE == 1) *(float4*)&eb[co*EP_STRIDE + p4*4] = v;
        }
    }
    if (MODE == 1) __syncthreads();
    if (MODE != 2){
        for (int it = tid; it < 32*64; it += NTHR){
            int c2 = it>>6, p4 = it&63;
            int px = p4*4;
            int hh = h0 + (p4>>5), w = (p4&31)*4;
            const float* e0 = &eb[(2*c2  )*EP_STRIDE + px];
            const float* e1 = &eb[(2*c2+1)*EP_STRIDE + px];
            uint4 o;
            o.x = pk2(e0[0], e1[0]); o.y = pk2(e0[1], e1[1]);
            o.z = pk2(e0[2], e1[2]); o.w = pk2(e0[3], e1[3]);
            *(uint4*)(outh + (((size_t)b*64 + ch*32 + c2)*HGT + hh)*WID + w) = o;
        }
    }
}

// ---------- launch ----------
extern "C" void kernel_launch(void* const* d_in, const int* in_sizes, int n_in,
                              void* d_out, int out_size)
{
    const float* x  = (const float*)d_in[0];
    const float* w1 = (const float*)d_in[1];
    const float* b1 = (const float*)d_in[2];
    const float* w2 = (const float*)d_in[3];
    const float* b2 = (const float*)d_in[4];
    float* out = (float*)d_out;

    float *gx; uint32_t *gxh, *gth, *gwph;
    cudaGetSymbolAddress((void**)&gx,   g_x);
    cudaGetSymbolAddress((void**)&gxh,  g_xh);
    cudaGetSymbolAddress((void**)&gth,  g_th);
    cudaGetSymbolAddress((void**)&gwph, g_wph);

    cudaFuncSetAttribute(conv_mma<0>, cudaFuncAttributeMaxDynamicSharedMemorySize, SMEM_DYN);
    cudaFuncSetAttribute(conv_mma<1>, cudaFuncAttributeMaxDynamicSharedMemorySize, SMEM_DYN);
    cudaFuncSetAttribute(conv_mma<2>, cudaFuncAttributeMaxDynamicSharedMemorySize, SMEM_DYN);

    pack_wh<<<(2*73728 + 255)/256, 256>>>(w1, w2, gwph);
    convert_x<<<4096, 256>>>(x, gxh);

    const uint32_t* wp1 = gwph;
    const uint32_t* wp2 = gwph + 73728;
    dim3 grid(HGT/2, BATCH, 2);

    conv_mma<0><<<grid, NTHR, SMEM_DYN>>>(gxh, wp1, b1, nullptr, nullptr, gth);
    conv_mma<1><<<grid, NTHR, SMEM_DYN>>>(gth, wp2, b2, x,       gx,      gxh);
    conv_mma<0><<<grid, NTHR, SMEM_DYN>>>(gxh, wp1, b1, nullptr, nullptr, gth);
    conv_mma<1><<<grid, NTHR, SMEM_DYN>>>(gth, wp2, b2, gx,      gx,      gxh);
    conv_mma<0><<<grid, NTHR, SMEM_DYN>>>(gxh, wp1, b1, nullptr, nullptr, gth);
    conv_mma<2><<<grid, NTHR, SMEM_DYN>>>(gth, wp2, b2, gx,      out,     nullptr);
}

// round 14
// speedup vs baseline: 2.2310x; 1.0697x over previous
#include <cuda_runtime.h>
#include <cuda_fp16.h>
#include <cstdint>

#define BATCH 16
#define CH    128
#define HGT   128
#define WID   128
#define NTHR  256

#define NSTAGE 12              // 3 kh * 4 ci-chunks (32 ci each)
#define A_W    3072            // 32-bit words of A per stage (fragment-packed half2)
#define B_ROW_W     272        // words per input row within a ci4 group (136 slots * 2)
#define B_CI4_STRIDE 552       // words per ci4 group (2*272 + 8 pad); 552%32==8 -> conflict-free LDS.64
#define SLOT_W (A_W + 8*B_CI4_STRIDE)    // 3072 + 4416 = 7488 words = 29952 B
#define SMEM_DYN (3*SLOT_W*4)            // 89856 B -> 2 CTAs/SM
#define EP_STRIDE 260

__device__ float    g_x  [(size_t)BATCH*CH*HGT*WID];     // fp32 state
__device__ uint32_t g_xh [(size_t)BATCH*32*HGT*WID*2];   // [b][ci4][h][w][2] half2 words
__device__ uint32_t g_th [(size_t)BATCH*32*HGT*WID*2];
__device__ uint32_t g_wph[2*2*12*3072];                  // packed fp16 weights

// ---------- helpers ----------
__device__ __forceinline__ uint32_t smem_u32(const void* p){
    uint32_t a; asm("{ .reg .u64 t; cvta.to.shared.u64 t, %1; cvt.u32.u64 %0, t; }":"=r"(a):"l"(p));
    return a;
}
__device__ __forceinline__ void cp16(uint32_t dst, const void* src, uint32_t ss){
    asm volatile("cp.async.cg.shared.global [%0], [%1], 16, %2;"
                 :: "r"(dst), "l"(src), "r"(ss) : "memory");
}
#define CP_COMMIT() asm volatile("cp.async.commit_group;":::"memory")
template<int N> __device__ __forceinline__ void cp_wait(){
    asm volatile("cp.async.wait_group %0;"::"n"(N):"memory");
}
__device__ __forceinline__ void mma16(float* d, const uint4& a, uint32_t b0, uint32_t b1){
    asm volatile("mma.sync.aligned.m16n8k16.row.col.f32.f16.f16.f32 "
        "{%0,%1,%2,%3}, {%4,%5,%6,%7}, {%8,%9}, {%0,%1,%2,%3};"
        : "+f"(d[0]), "+f"(d[1]), "+f"(d[2]), "+f"(d[3])
        : "r"(a.x), "r"(a.y), "r"(a.z), "r"(a.w), "r"(b0), "r"(b1));
}
// pack two fp32 -> half2 word, low half = lo
__device__ __forceinline__ uint32_t pk2(float lo, float hi){
    uint32_t r;
    asm("cvt.rn.f16x2.f32 %0, %1, %2;" : "=r"(r) : "f"(hi), "f"(lo));
    return r;
}

// ---------- weight pack: fp16 fragment layout, channel-quad k-mapping ----------
// word idx: [set][ch][s(12)][kw(3)][j(2)][m16(4)][lane(32)][rr(4)]
// k-map: for j-half, lane t: k=(2t,2t+1) -> ch 4*(4j+t)+0,1 ; k=(2t+8,2t+9) -> +2,3
__global__ void pack_wh(const float* __restrict__ w1, const float* __restrict__ w2,
                        uint32_t* __restrict__ dst){
    int idx = blockIdx.x*blockDim.x + threadIdx.x;
    if (idx >= 2*73728) return;
    int r = idx;
    int set = r / 73728; r %= 73728;
    int ch  = r / 36864; r %= 36864;
    int s   = r / 3072;  r %= 3072;
    int kw  = r / 1024;  r %= 1024;
    int j   = r / 512;   r %= 512;
    int m16 = r / 128;   r %= 128;
    int lane = r >> 2;
    int rr   = r & 3;
    int g = lane>>2, t = lane&3;
    int co = ch*64 + m16*16 + g + ((rr&1)<<3);
    int kh = s>>2, chunk = s&3;
    int ci = chunk*32 + (j*4 + t)*4 + ((rr>>1)<<1);   // quad base + k-half offset
    const float* w = set ? w2 : w1;
    float lo = w[((size_t)co*CH + ci  )*9 + kh*3 + kw];
    float hi = w[((size_t)co*CH + ci+1)*9 + kh*3 + kw];
    dst[idx] = pk2(lo, hi);
}

// ---------- convert x -> [b][ci4][h][w][2] half2 words ----------
__global__ void convert_x(const float* __restrict__ in, uint32_t* __restrict__ out){
    const int total = BATCH*32*HGT*(WID/2);   // each item: uint4 = 2 px * 2 words
    for (int i = blockIdx.x*blockDim.x + threadIdx.x; i < total; i += gridDim.x*blockDim.x){
        int wp = i & 63; int r = i >> 6;
        int h  = r & 127; r >>= 7;
        int ci4 = r & 31; int b = r >> 5;
        int c0 = 4*ci4, w0 = wp*2;
        const float* p = in + (((size_t)b*CH + c0)*HGT + h)*WID + w0;
        const size_t cs = (size_t)HGT*WID;
        float2 v0 = *(const float2*)(p);
        float2 v1 = *(const float2*)(p + cs);
        float2 v2 = *(const float2*)(p + 2*cs);
        float2 v3 = *(const float2*)(p + 3*cs);
        uint4 o;
        o.x = pk2(v0.x, v1.x); o.y = pk2(v2.x, v3.x);   // px w0:  word0=(c0,c1), word1=(c2,c3)
        o.z = pk2(v0.y, v1.y); o.w = pk2(v2.y, v3.y);   // px w0+1
        *(uint4*)(out + ((((size_t)b*32 + ci4)*HGT + h)*WID + w0)*2) = o;
    }
}

// ---------- conv kernel ----------
// MODE 0: t = relu(conv+b)            -> outh only
// MODE 1: v = xadd + (conv+b)/3       -> outf (fp32) + outh
// MODE 2: v = relu(xadd + (conv+b)/3) -> outf only
template<int MODE>
__global__ void __launch_bounds__(NTHR, 2)
conv_mma(const uint32_t* __restrict__ inh, const uint32_t* __restrict__ wph,
         const float* __restrict__ bias, const float* __restrict__ xadd,
         float* __restrict__ outf, uint32_t* __restrict__ outh)
{
    extern __shared__ __align__(1024) float sm[];
    uint32_t* smw = (uint32_t*)sm;
    const int tid = threadIdx.x, lane = tid&31, wid = tid>>5;
    const int g = lane>>2, t = lane&3;
    const int wm = wid&1, wn = wid>>1;
    const int brow = wn>>1, nb = (wn&1)*64;
    const int h0 = blockIdx.x*2, b = blockIdx.y, ch = blockIdx.z;
    const uint32_t* in_b = inh + (size_t)b*32*HGT*WID*2;
    const uint32_t* wpc  = wph + (size_t)ch*36864;

    float d[2][8][4];
#pragma unroll
    for (int mt=0;mt<2;mt++)
#pragma unroll
        for (int nt=0;nt<8;nt++)
#pragma unroll
            for (int c=0;c<4;c++) d[mt][nt][c] = 0.f;

    auto issue_stage = [&](int s, int slot){
        uint32_t* sl = smw + slot*SLOT_W;
        uint32_t base = smem_u32(sl);
        // A: 3072 words = 768 cp16
        const uint32_t* asrc = wpc + (size_t)s*3072;
#pragma unroll
        for (int i=0;i<3;i++){
            int u = tid + i*256;
            cp16(base + u*16, asrc + u*4, 16);
        }
        // B: 8 ci4 x 2 rows x 64 chunks (2px*2words) = 1024 cp16
        const int kh = s>>2, chunk = s&3;
#pragma unroll
        for (int i=0;i<4;i++){
            int v = tid + i*256;
            int ci4 = v>>7, rem = v&127, row = rem>>6, cw = rem&63;
            int r = h0 + kh - 1 + row;
            uint32_t ss = ((unsigned)r < HGT) ? 16u : 0u;
            int rc = ((unsigned)r < HGT) ? r : 0;
            const uint32_t* src = in_b + ((((size_t)(chunk*8+ci4))*HGT + rc)*WID + 2*cw)*2;
            cp16(base + (A_W + ci4*B_CI4_STRIDE + row*B_ROW_W + 8 + 4*cw)*4, src, ss);
        }
        // halo zeros: slot 3 (px=-1) words 6,7 ; slot 132 (px=128) words 264,265
        if (tid < 64){
            int ci4 = tid>>3, r3 = tid&7;
            int row = r3>>2, q = r3&3;
            int wd = ((q>>1) ? 264 : 6) + (q&1);
            sl[A_W + ci4*B_CI4_STRIDE + row*B_ROW_W + wd] = 0;
        }
    };

    issue_stage(0, 0); CP_COMMIT();
    issue_stage(1, 1); CP_COMMIT();

    int slot = 0;
    for (int s=0; s<NSTAGE; s++){
        if (s < NSTAGE-2) cp_wait<1>(); else cp_wait<0>();
        __syncthreads();

        const uint32_t* A  = smw + slot*SLOT_W;
        const uint32_t* Bb = A + A_W;
#pragma unroll
        for (int j=0; j<2; j++){
            // px p -> word (p+4)*2 ; read px = nb+g+kw+8nt-1 -> word base (nb+g+3)*2
            const uint32_t* bt = Bb + (j*4+t)*B_CI4_STRIDE + brow*B_ROW_W + (nb + g + 3)*2;
#pragma unroll
            for (int kw=0; kw<3; kw++){
                uint4 av[2];
#pragma unroll
                for (int mt=0; mt<2; mt++)
                    av[mt] = *(const uint4*)(A + ((kw*2+j)*4 + wm*2+mt)*128 + lane*4);
#pragma unroll
                for (int nt=0; nt<8; nt++){
                    uint2 bb = *(const uint2*)(bt + (kw + 8*nt)*2);
                    mma16(d[0][nt], av[0], bb.x, bb.y);
                    mma16(d[1][nt], av[1], bb.x, bb.y);
                }
            }
        }

        if (s < NSTAGE-2){
            int nslot = slot+2; if (nslot >= 3) nslot -= 3;
            issue_stage(s+2, nslot);
            CP_COMMIT();
        }
        slot = (slot+1 == 3) ? 0 : slot+1;
    }

    // ---- epilogue ----
    __syncthreads();
    float* eb = sm;   // 64co x 256px, stride EP_STRIDE
#pragma unroll
    for (int mt=0; mt<2; mt++){
        const int r0 = wm*32 + mt*16 + g;
        const float bv0 = bias[ch*64 + r0];
        const float bv1 = bias[ch*64 + r0 + 8];
        const int a0 = r0*EP_STRIDE + brow*128 + nb + 2*t;
#pragma unroll
        for (int nt=0; nt<8; nt++){
            float v0 = d[mt][nt][0] + bv0, v1 = d[mt][nt][1] + bv0;
            float v2 = d[mt][nt][2] + bv1, v3 = d[mt][nt][3] + bv1;
            if (MODE == 0){
                v0 = fmaxf(v0,0.f); v1 = fmaxf(v1,0.f);
                v2 = fmaxf(v2,0.f); v3 = fmaxf(v3,0.f);
            }
            eb[a0 + nt*8]                  = v0;
            eb[a0 + nt*8 + 1]              = v1;
            eb[a0 + 8*EP_STRIDE + nt*8]    = v2;
            eb[a0 + 8*EP_STRIDE + nt*8 +1] = v3;
        }
    }
    __syncthreads();

    const float inv3 = 1.0f/3.0f;
    if (MODE != 0){
        for (int it = tid; it < 64*64; it += NTHR){
            int co = it>>6, p4 = it&63;
            float4 v = *(const float4*)&eb[co*EP_STRIDE + p4*4];
            int hh = h0 + (p4>>5), w = (p4&31)*4;
            size_t gi = (((size_t)b*CH + ch*64 + co)*HGT + hh)*WID + w;
            float4 xv = *(const float4*)&xadd[gi];
            v.x = xv.x + inv3*v.x; v.y = xv.y + inv3*v.y;
            v.z = xv.z + inv3*v.z; v.w = xv.w + inv3*v.w;
            if (MODE == 2){
                v.x = fmaxf(v.x,0.f); v.y = fmaxf(v.y,0.f);
                v.z = fmaxf(v.z,0.f); v.w = fmaxf(v.w,0.f);
            }
            *(float4*)&outf[gi] = v;
            if (MODE == 1) *(float4*)&eb[co*EP_STRIDE + p4*4] = v;
        }
    }
    if (MODE == 1) __syncthreads();
    if (MODE != 2){
        // emit [b][ci4][h][w][2]: 16 ci4-groups (this ch half) x 2 rows x 64 wpairs
        for (int it = tid; it < 2048; it += NTHR){
            int wp = it & 63; int r = it >> 6;
            int row = r & 1; int q = r >> 1;        // q = 0..15
            int p = row*128 + wp*2;                 // eb px index
            const float* e0 = &eb[(4*q  )*EP_STRIDE + p];
            const float* e1 = &eb[(4*q+1)*EP_STRIDE + p];
            const float* e2 = &eb[(4*q+2)*EP_STRIDE + p];
            const float* e3 = &eb[(4*q+3)*EP_STRIDE + p];
            uint4 o;
            o.x = pk2(e0[0], e1[0]); o.y = pk2(e2[0], e3[0]);
            o.z = pk2(e0[1], e1[1]); o.w = pk2(e2[1], e3[1]);
            *(uint4*)(outh + ((((size_t)b*32 + ch*16 + q)*HGT + (h0+row))*WID + wp*2)*2) = o;
        }
    }
}

// ---------- launch ----------
extern "C" void kernel_launch(void* const* d_in, const int* in_sizes, int n_in,
                              void* d_out, int out_size)
{
    const float* x  = (const float*)d_in[0];
    const float* w1 = (const float*)d_in[1];
    const float* b1 = (const float*)d_in[2];
    const float* w2 = (const float*)d_in[3];
    const float* b2 = (const float*)d_in[4];
    float* out = (float*)d_out;

    float *gx; uint32_t *gxh, *gth, *gwph;
    cudaGetSymbolAddress((void**)&gx,   g_x);
    cudaGetSymbolAddress((void**)&gxh,  g_xh);
    cudaGetSymbolAddress((void**)&gth,  g_th);
    cudaGetSymbolAddress((void**)&gwph, g_wph);

    cudaFuncSetAttribute(conv_mma<0>, cudaFuncAttributeMaxDynamicSharedMemorySize, SMEM_DYN);
    cudaFuncSetAttribute(conv_mma<1>, cudaFuncAttributeMaxDynamicSharedMemorySize, SMEM_DYN);
    cudaFuncSetAttribute(conv_mma<2>, cudaFuncAttributeMaxDynamicSharedMemorySize, SMEM_DYN);

    pack_wh<<<(2*73728 + 255)/256, 256>>>(w1, w2, gwph);
    convert_x<<<4096, 256>>>(x, gxh);

    const uint32_t* wp1 = gwph;
    const uint32_t* wp2 = gwph + 73728;
    dim3 grid(HGT/2, BATCH, 2);

    conv_mma<0><<<grid, NTHR, SMEM_DYN>>>(gxh, wp1, b1, nullptr, nullptr, gth);
    conv_mma<1><<<grid, NTHR, SMEM_DYN>>>(gth, wp2, b2, x,       gx,      gxh);
    conv_mma<0><<<grid, NTHR, SMEM_DYN>>>(gxh, wp1, b1, nullptr, nullptr, gth);
    conv_mma<1><<<grid, NTHR, SMEM_DYN>>>(gth, wp2, b2, gx,      gx,      gxh);
    conv_mma<0><<<grid, NTHR, SMEM_DYN>>>(gxh, wp1, b1, nullptr, nullptr, gth);
    conv_mma<2><<<grid, NTHR, SMEM_DYN>>>(gth, wp2, b2, gx,      out,     nullptr);
}